// round 1
// baseline (speedup 1.0000x reference)
#include <cuda_runtime.h>
#include <math.h>

// Problem constants (LSTM_Layer_2576980377766)
#define BB   64          // batch
#define TT   512         // timesteps
#define DD   512         // input dim
#define UU   1024        // hidden units
#define G4   4096        // 4*UU

// ---------------- scratch (device globals; no allocation allowed) ----------
__device__ float g_xg[(size_t)BB * TT * G4];   // 512 MB: precomputed x@Wx + b
__device__ float g_h[2][BB * UU];              // double-buffered hidden state
__device__ float g_c[BB * UU];                 // cell state

// ---------------- helpers ---------------------------------------------------
__device__ __forceinline__ unsigned f2tf(float x) {
    unsigned u;
    asm("cvt.rna.tf32.f32 %0, %1;" : "=r"(u) : "f"(x));
    return u;
}

__device__ __forceinline__ void mma_tf32(float c[4], const unsigned a[4], const unsigned b[2]) {
    asm volatile(
        "mma.sync.aligned.m16n8k8.row.col.f32.tf32.tf32.f32 "
        "{%0,%1,%2,%3}, {%4,%5,%6,%7}, {%8,%9}, {%0,%1,%2,%3};"
        : "+f"(c[0]), "+f"(c[1]), "+f"(c[2]), "+f"(c[3])
        : "r"(a[0]), "r"(a[1]), "r"(a[2]), "r"(a[3]), "r"(b[0]), "r"(b[1]));
}

__device__ __forceinline__ float sigmoidf_(float x) { return 1.0f / (1.0f + expf(-x)); }

// ============================================================================
// Kernel 1: xg[r, n] = x[r, :] @ Wx[:, n] + b[n]      (r = b*TT + t)
// CTA tile 64x64, K-chunk 32, TF32 mma. Grid (512, 64), 256 threads.
// ============================================================================
__global__ __launch_bounds__(256) void xg_kernel(
    const float* __restrict__ x, const float* __restrict__ Wx,
    const float* __restrict__ b)
{
    __shared__ unsigned As[64 * 36];  // [m][k] stride 36 (conflict-free)
    __shared__ unsigned Bs[32 * 72];  // [k][n] stride 72 (conflict-free)

    const int tid  = threadIdx.x;
    const int warp = tid >> 5, lane = tid & 31;
    const int lr = lane >> 2, lc = lane & 3;
    const int mo = (warp & 3) * 16;        // 4 warps along M
    const int no = (warp >> 2) * 32;       // 2 warps along N, 32 cols each

    const int r0 = blockIdx.x * 64;
    const int n0 = blockIdx.y * 64;

    float c[4][4];
#pragma unroll
    for (int j = 0; j < 4; j++)
#pragma unroll
        for (int i = 0; i < 4; i++) c[j][i] = 0.0f;

    for (int kc = 0; kc < DD / 32; kc++) {
        const int k0 = kc * 32;
        __syncthreads();
        // fill A: 64 rows x 32 cols (float4, 2 per thread)
        {
            int rr = tid >> 3, c4 = tid & 7;
#pragma unroll
            for (int p = 0; p < 2; p++) {
                int r = rr + p * 32;
                float4 v = *reinterpret_cast<const float4*>(&x[(size_t)(r0 + r) * DD + k0 + c4 * 4]);
                unsigned* d = &As[r * 36 + c4 * 4];
                d[0] = f2tf(v.x); d[1] = f2tf(v.y); d[2] = f2tf(v.z); d[3] = f2tf(v.w);
            }
        }
        // fill B: 32 rows x 64 cols (float4, 2 per thread)
        {
            int kk = tid >> 4, c4 = tid & 15;
#pragma unroll
            for (int p = 0; p < 2; p++) {
                int k = kk + p * 16;
                float4 v = *reinterpret_cast<const float4*>(&Wx[(size_t)(k0 + k) * G4 + n0 + c4 * 4]);
                unsigned* d = &Bs[k * 72 + c4 * 4];
                d[0] = f2tf(v.x); d[1] = f2tf(v.y); d[2] = f2tf(v.z); d[3] = f2tf(v.w);
            }
        }
        __syncthreads();
#pragma unroll
        for (int ks = 0; ks < 4; ks++) {
            const int kk = ks * 8;
            unsigned a[4];
            a[0] = As[(mo + lr) * 36 + kk + lc];
            a[1] = As[(mo + lr + 8) * 36 + kk + lc];
            a[2] = As[(mo + lr) * 36 + kk + lc + 4];
            a[3] = As[(mo + lr + 8) * 36 + kk + lc + 4];
#pragma unroll
            for (int j = 0; j < 4; j++) {
                unsigned bb[2];
                bb[0] = Bs[(kk + lc) * 72 + no + j * 8 + lr];
                bb[1] = Bs[(kk + lc + 4) * 72 + no + j * 8 + lr];
                mma_tf32(c[j], a, bb);
            }
        }
    }

    // epilogue: += bias, store float2 pairs
    const int rA = r0 + mo + lr;
#pragma unroll
    for (int j = 0; j < 4; j++) {
        const int cl = no + j * 8 + 2 * lc;
        const int n  = n0 + cl;
        const float b0 = b[n], b1 = b[n + 1];
        float2 v0 = make_float2(c[j][0] + b0, c[j][1] + b1);
        float2 v1 = make_float2(c[j][2] + b0, c[j][3] + b1);
        *reinterpret_cast<float2*>(&g_xg[(size_t)rA * G4 + n])        = v0;
        *reinterpret_cast<float2*>(&g_xg[(size_t)(rA + 8) * G4 + n])  = v1;
    }
}

// ============================================================================
// Kernel 2: one LSTM timestep.
// CTA owns u-slice of 8 hidden units -> 32 gate columns (i,f,g,o x 8).
// gates[64,32] = h[64,1024] @ Wh[:, slice] + xg[:, t, slice]; then cell update.
// Grid 128 CTAs, 256 threads.
// ============================================================================
__global__ __launch_bounds__(256) void step_kernel(
    const float* __restrict__ Wh, int t)
{
    __shared__ unsigned Hs[64 * 36];   // [m][k]
    __shared__ unsigned Ws[32 * 40];   // [k][n_local]
    __shared__ float    Gs[64 * 33];   // gates

    const int tid  = threadIdx.x;
    const int warp = tid >> 5, lane = tid & 31;
    const int lr = lane >> 2, lc = lane & 3;
    const int mo = (warp & 3) * 16;      // 4 warps along M(=batch 64)
    const int no = (warp >> 2) * 16;     // 2 warps along N, 16 cols each
    const int u0 = blockIdx.x * 8;       // u-slice
    const int p  = t & 1;
    const float* __restrict__ hcur = g_h[p];
    float* __restrict__       hnxt = g_h[p ^ 1];

    float c[2][4];
#pragma unroll
    for (int j = 0; j < 2; j++)
#pragma unroll
        for (int i = 0; i < 4; i++) c[j][i] = 0.0f;

    for (int kc = 0; kc < UU / 32; kc++) {
        const int k0 = kc * 32;
        __syncthreads();
        // fill H: 64 rows x 32 cols (float4, 2 per thread)
        {
            int rr = tid >> 3, c4 = tid & 7;
#pragma unroll
            for (int q = 0; q < 2; q++) {
                int r = rr + q * 32;
                float4 v = *reinterpret_cast<const float4*>(&hcur[(size_t)r * UU + k0 + c4 * 4]);
                unsigned* d = &Hs[r * 36 + c4 * 4];
                d[0] = f2tf(v.x); d[1] = f2tf(v.y); d[2] = f2tf(v.z); d[3] = f2tf(v.w);
            }
        }
        // fill W: 32 rows x 32 cols; n_local nn -> global col gate*UU + u0 + (nn&7)
        {
            int kk = tid >> 3, q = tid & 7;
            int nn = q * 4;                      // 0,4,...,28 (stays within one gate 8-block)
            int gate = nn >> 3, du = nn & 7;
            float4 v = *reinterpret_cast<const float4*>(
                &Wh[(size_t)(k0 + kk) * G4 + gate * UU + u0 + du]);
            unsigned* d = &Ws[kk * 40 + nn];
            d[0] = f2tf(v.x); d[1] = f2tf(v.y); d[2] = f2tf(v.z); d[3] = f2tf(v.w);
        }
        __syncthreads();
#pragma unroll
        for (int ks = 0; ks < 4; ks++) {
            const int kk = ks * 8;
            unsigned a[4];
            a[0] = Hs[(mo + lr) * 36 + kk + lc];
            a[1] = Hs[(mo + lr + 8) * 36 + kk + lc];
            a[2] = Hs[(mo + lr) * 36 + kk + lc + 4];
            a[3] = Hs[(mo + lr + 8) * 36 + kk + lc + 4];
#pragma unroll
            for (int j = 0; j < 2; j++) {
                unsigned bb[2];
                bb[0] = Ws[(kk + lc) * 40 + no + j * 8 + lr];
                bb[1] = Ws[(kk + lc + 4) * 40 + no + j * 8 + lr];
                mma_tf32(c[j], a, bb);
            }
        }
    }

    // epilogue: gates = C + xg, into SMEM
    const int rA = mo + lr;
#pragma unroll
    for (int j = 0; j < 2; j++) {
        const int cl = no + j * 8 + 2 * lc;           // n_local (cl, cl+1 same gate)
        const int gate = cl >> 3, du = cl & 7;
        const size_t base0 = ((size_t)(rA * TT + t)) * G4 + (size_t)gate * UU + u0 + du;
        const size_t base1 = ((size_t)((rA + 8) * TT + t)) * G4 + (size_t)gate * UU + u0 + du;
        Gs[rA * 33 + cl]           = c[j][0] + g_xg[base0];
        Gs[rA * 33 + cl + 1]       = c[j][1] + g_xg[base0 + 1];
        Gs[(rA + 8) * 33 + cl]     = c[j][2] + g_xg[base1];
        Gs[(rA + 8) * 33 + cl + 1] = c[j][3] + g_xg[base1 + 1];
    }
    __syncthreads();

    // elementwise LSTM cell: 64 batch x 8 units = 512 elems, 2 per thread
#pragma unroll
    for (int q = 0; q < 2; q++) {
        int e  = tid + q * 256;
        int m  = e >> 3, du = e & 7;
        float gi = sigmoidf_(Gs[m * 33 + 0 * 8 + du]);
        float gf = sigmoidf_(Gs[m * 33 + 1 * 8 + du]);
        float gg = tanhf   (Gs[m * 33 + 2 * 8 + du]);
        float go = sigmoidf_(Gs[m * 33 + 3 * 8 + du]);
        int idx = m * UU + u0 + du;
        float cv = gf * g_c[idx] + gi * gg;
        g_c[idx] = cv;
        hnxt[idx] = go * tanhf(cv);
    }
}

// ============================================================================
extern "C" void kernel_launch(void* const* d_in, const int* in_sizes, int n_in,
                              void* d_out, int out_size)
{
    const float* x  = (const float*)d_in[0];
    const float* h0 = (const float*)d_in[1];
    const float* c0 = (const float*)d_in[2];
    const float* Wx = (const float*)d_in[3];
    const float* Wh = (const float*)d_in[4];
    const float* b  = (const float*)d_in[5];
    float* out = (float*)d_out;

    // init state from inputs (every call: graph replays must reset state)
    cudaMemcpyToSymbolAsync(g_h, h0, (size_t)BB * UU * sizeof(float), 0,
                            cudaMemcpyDeviceToDevice, 0);
    cudaMemcpyToSymbolAsync(g_c, c0, (size_t)BB * UU * sizeof(float), 0,
                            cudaMemcpyDeviceToDevice, 0);

    // phase 1: xg = x @ Wx + b
    {
        dim3 grid(BB * TT / 64, G4 / 64);
        xg_kernel<<<grid, 256>>>(x, Wx, b);
    }

    // phase 2: 512 sequential timesteps
    for (int t = 0; t < TT; t++) {
        step_kernel<<<UU / 8, 256>>>(Wh, t);
    }

    // final h lives in g_h[0] (t=511 writes parity (511+1)&1 = 0)
    cudaMemcpyFromSymbolAsync(out, g_h, (size_t)BB * UU * sizeof(float), 0,
                              cudaMemcpyDeviceToDevice, 0);
    (void)in_sizes; (void)n_in; (void)out_size;
}

// round 2
// speedup vs baseline: 1.7146x; 1.7146x over previous
#include <cuda_runtime.h>
#include <math.h>

// Problem constants (LSTM_Layer_2576980377766)
#define BB   64          // batch
#define TT   512         // timesteps
#define DD   512         // input dim
#define UU   1024        // hidden units
#define G4   4096        // 4*UU
#define NCTA 128         // persistent CTAs (<= 148 SMs, co-resident)

// ---------------- scratch (device globals; no allocation allowed) ----------
__device__ float g_xg[(size_t)BB * TT * G4];   // 512 MB: x@Wx + b, layout [t][b][4096]
__device__ float g_h[2][BB * UU];              // double-buffered hidden state
__device__ volatile unsigned g_bar_gen = 0;    // grid barrier generation
__device__ unsigned g_bar_cnt = 0;             // grid barrier arrival count

// ---------------- helpers ---------------------------------------------------
__device__ __forceinline__ unsigned f2tf(float x) {
    unsigned u;
    asm("cvt.rna.tf32.f32 %0, %1;" : "=r"(u) : "f"(x));
    return u;
}

__device__ __forceinline__ void mma_tf32(float c[4], const unsigned a0, const unsigned a1,
                                         const unsigned a2, const unsigned a3,
                                         const unsigned b0, const unsigned b1) {
    asm volatile(
        "mma.sync.aligned.m16n8k8.row.col.f32.tf32.tf32.f32 "
        "{%0,%1,%2,%3}, {%4,%5,%6,%7}, {%8,%9}, {%0,%1,%2,%3};"
        : "+f"(c[0]), "+f"(c[1]), "+f"(c[2]), "+f"(c[3])
        : "r"(a0), "r"(a1), "r"(a2), "r"(a3), "r"(b0), "r"(b1));
}

__device__ __forceinline__ uint4 ldsm4(unsigned addr) {
    uint4 r;
    asm volatile("ldmatrix.sync.aligned.m8n8.x4.shared.b16 {%0,%1,%2,%3}, [%4];"
                 : "=r"(r.x), "=r"(r.y), "=r"(r.z), "=r"(r.w) : "r"(addr));
    return r;
}

__device__ __forceinline__ float sigmoidf_(float x) { return 1.0f / (1.0f + expf(-x)); }

// ============================================================================
// Kernel 1: xg[t, b, n] = x[b, t, :] @ Wx[:, n] + b[n]
// CTA tile 64x64 over rows r = b*TT+t, TF32 mma. Grid (512, 64), 256 threads.
// ============================================================================
__global__ __launch_bounds__(256) void xg_kernel(
    const float* __restrict__ x, const float* __restrict__ Wx,
    const float* __restrict__ b)
{
    __shared__ unsigned As[64 * 36];
    __shared__ unsigned Bs[32 * 72];

    const int tid  = threadIdx.x;
    const int warp = tid >> 5, lane = tid & 31;
    const int lr = lane >> 2, lc = lane & 3;
    const int mo = (warp & 3) * 16;
    const int no = (warp >> 2) * 32;

    const int r0 = blockIdx.x * 64;
    const int n0 = blockIdx.y * 64;

    float c[4][4];
#pragma unroll
    for (int j = 0; j < 4; j++)
#pragma unroll
        for (int i = 0; i < 4; i++) c[j][i] = 0.0f;

    for (int kc = 0; kc < DD / 32; kc++) {
        const int k0 = kc * 32;
        __syncthreads();
        {
            int rr = tid >> 3, c4 = tid & 7;
#pragma unroll
            for (int p = 0; p < 2; p++) {
                int r = rr + p * 32;
                float4 v = *reinterpret_cast<const float4*>(&x[(size_t)(r0 + r) * DD + k0 + c4 * 4]);
                unsigned* d = &As[r * 36 + c4 * 4];
                d[0] = f2tf(v.x); d[1] = f2tf(v.y); d[2] = f2tf(v.z); d[3] = f2tf(v.w);
            }
        }
        {
            int kk = tid >> 4, c4 = tid & 15;
#pragma unroll
            for (int p = 0; p < 2; p++) {
                int k = kk + p * 16;
                float4 v = *reinterpret_cast<const float4*>(&Wx[(size_t)(k0 + k) * G4 + n0 + c4 * 4]);
                unsigned* d = &Bs[k * 72 + c4 * 4];
                d[0] = f2tf(v.x); d[1] = f2tf(v.y); d[2] = f2tf(v.z); d[3] = f2tf(v.w);
            }
        }
        __syncthreads();
#pragma unroll
        for (int ks = 0; ks < 4; ks++) {
            const int kk = ks * 8;
            unsigned a0 = As[(mo + lr) * 36 + kk + lc];
            unsigned a1 = As[(mo + lr + 8) * 36 + kk + lc];
            unsigned a2 = As[(mo + lr) * 36 + kk + lc + 4];
            unsigned a3 = As[(mo + lr + 8) * 36 + kk + lc + 4];
#pragma unroll
            for (int j = 0; j < 4; j++) {
                unsigned b0 = Bs[(kk + lc) * 72 + no + j * 8 + lr];
                unsigned b1 = Bs[(kk + lc + 4) * 72 + no + j * 8 + lr];
                mma_tf32(c[j], a0, a1, a2, a3, b0, b1);
            }
        }
    }

    // epilogue: += bias, store to g_xg[t][b][n] layout
    const int rA = r0 + mo + lr;       // rA = b*TT + t
    const int bA0 = rA >> 9, tA0 = rA & (TT - 1);
    const int rB  = rA + 8;
    const int bA1 = rB >> 9, tA1 = rB & (TT - 1);
    const size_t row0 = (size_t)(tA0 * BB + bA0) * G4;
    const size_t row1 = (size_t)(tA1 * BB + bA1) * G4;
#pragma unroll
    for (int j = 0; j < 4; j++) {
        const int cl = no + j * 8 + 2 * lc;
        const int n  = n0 + cl;
        const float b0 = b[n], b1 = b[n + 1];
        *reinterpret_cast<float2*>(&g_xg[row0 + n]) = make_float2(c[j][0] + b0, c[j][1] + b1);
        *reinterpret_cast<float2*>(&g_xg[row1 + n]) = make_float2(c[j][2] + b0, c[j][3] + b1);
    }
}

// ============================================================================
// Kernel 2: persistent LSTM recurrence. 128 CTAs x 256 threads.
// CTA owns u-slice of 8 hidden units -> 32 gate columns (i,f,g,o x 8).
// Wh slice kept in SMEM (tf32, n-major) for all 512 steps.
// Per step: gates[64,32] = h @ Whs + xg[t]; cell update; grid barrier.
// ============================================================================
#define WT_STRIDE 1028                 // floats per n-row of Wt (1024 + 4 pad)
#define HS_STRIDE 36                   // floats per m-row of Hs chunk (32 + 4 pad)
#define HS_ELEMS  (64 * HS_STRIDE)     // one chunk buffer
#define SMEM_WORDS (32 * WT_STRIDE + 2 * HS_ELEMS + 64 * 33 + 64 * 8)
#define SMEM_BYTES (SMEM_WORDS * 4)

__device__ __forceinline__ void grid_bar() {
    __syncthreads();
    if (threadIdx.x == 0) {
        unsigned gen = g_bar_gen;
        __threadfence();                                  // release h writes
        if (atomicAdd(&g_bar_cnt, 1u) == NCTA - 1u) {
            g_bar_cnt = 0;
            __threadfence();
            g_bar_gen = gen + 1;                          // release
        } else {
            while (g_bar_gen == gen) { __nanosleep(40); }
        }
        __threadfence();                                  // acquire
    }
    __syncthreads();
}

__global__ __launch_bounds__(256) void lstm_persist(
    const float* __restrict__ Wh, const float* __restrict__ c0)
{
    extern __shared__ unsigned smem[];
    unsigned* Wt = smem;                           // [32][WT_STRIDE] tf32, n-major
    unsigned* Hs = Wt + 32 * WT_STRIDE;            // 2 x [64][HS_STRIDE] tf32
    float*    Gs = (float*)(Hs + 2 * HS_ELEMS);    // [64][33] gates
    float*    Cl = Gs + 64 * 33;                   // [64][8] cell state slice

    const int tid  = threadIdx.x;
    const int warp = tid >> 5, lane = tid & 31;
    const int lr = lane >> 2, lc = lane & 3;
    const int mo = (warp & 3) * 16;                // 4 warps along M (batch)
    const int no = (warp >> 2) * 16;               // 2 warps along N, 16 cols
    const int u0 = blockIdx.x * 8;                 // this CTA's u-slice

    const unsigned HsB = (unsigned)__cvta_generic_to_shared(Hs);
    const unsigned WtB = (unsigned)__cvta_generic_to_shared(Wt);

    // per-lane ldmatrix row/col assignments
    const int g8   = lane >> 3;                                   // matrix index 0..3
    const int rowA = mo + (g8 & 1) * 8 + (lane & 7);              // A: m row
    const int kAo  = (g8 >> 1) * 4;                               // A: k sub-offset
    const int rowB = no + (g8 >> 1) * 8 + (lane & 7);             // B: n row
    const int kBo  = (g8 & 1) * 4;                                // B: k sub-offset

    // ---- one-time: stage Wh slice into SMEM as tf32, n-major [n][k] ----
    for (int i = tid; i < 1024 * 32; i += 256) {
        int k = i >> 5, n = i & 31;
        int gate = n >> 3, du = n & 7;
        float v = Wh[(size_t)k * G4 + gate * UU + u0 + du];
        Wt[n * WT_STRIDE + k] = f2tf(v);
    }
    // ---- one-time: load cell-state slice ----
    for (int i = tid; i < 512; i += 256) {
        int m = i >> 3, du = i & 7;
        Cl[i] = c0[m * UU + u0 + du];
    }
    __syncthreads();

    const int rr = tid >> 3, c4 = tid & 7;         // h-chunk staging roles

    for (int t = 0; t < TT; t++) {
        const float* __restrict__ hcur = g_h[t & 1];
        float*       __restrict__ hnxt = g_h[(t + 1) & 1];

        // prefetch xg values for this step's epilogue (8 scalars per lane)
        float xv[2][4];
        {
            const size_t base = (size_t)t * BB * G4;
#pragma unroll
            for (int j = 0; j < 2; j++) {
                const int cl = no + j * 8 + 2 * lc;
                const int colg = (cl >> 3) * UU + u0 + (cl & 7);
                const size_t r0 = base + (size_t)(mo + lr) * G4 + colg;
                const size_t r1 = base + (size_t)(mo + lr + 8) * G4 + colg;
                xv[j][0] = g_xg[r0];     xv[j][1] = g_xg[r0 + 1];
                xv[j][2] = g_xg[r1];     xv[j][3] = g_xg[r1 + 1];
            }
        }

        float acc[2][4];
#pragma unroll
        for (int j = 0; j < 2; j++)
#pragma unroll
            for (int i = 0; i < 4; i++) acc[j][i] = 0.0f;

        // preload chunk 0
        float4 v0 = *reinterpret_cast<const float4*>(&hcur[(size_t)rr * UU + c4 * 4]);
        float4 v1 = *reinterpret_cast<const float4*>(&hcur[(size_t)(rr + 32) * UU + c4 * 4]);

        for (int kc = 0; kc < UU / 32; kc++) {
            const unsigned bufB = HsB + (kc & 1) * HS_ELEMS * 4;
            // store staged chunk (cvt to tf32), conflict-free stride 36
            {
                uint4 s;
                s.x = f2tf(v0.x); s.y = f2tf(v0.y); s.z = f2tf(v0.z); s.w = f2tf(v0.w);
                *reinterpret_cast<uint4*>(&Hs[(kc & 1) * HS_ELEMS + rr * HS_STRIDE + c4 * 4]) = s;
                s.x = f2tf(v1.x); s.y = f2tf(v1.y); s.z = f2tf(v1.z); s.w = f2tf(v1.w);
                *reinterpret_cast<uint4*>(&Hs[(kc & 1) * HS_ELEMS + (rr + 32) * HS_STRIDE + c4 * 4]) = s;
            }
            __syncthreads();
            // prefetch next chunk (hidden behind the mma below)
            if (kc < UU / 32 - 1) {
                const int k0 = (kc + 1) * 32;
                v0 = *reinterpret_cast<const float4*>(&hcur[(size_t)rr * UU + k0 + c4 * 4]);
                v1 = *reinterpret_cast<const float4*>(&hcur[(size_t)(rr + 32) * UU + k0 + c4 * 4]);
            }
            const int kbase = kc * 32;
#pragma unroll
            for (int ks = 0; ks < 4; ks++) {
                const int kk = ks * 8;
                uint4 A = ldsm4(bufB + (unsigned)(rowA * HS_STRIDE + kk + kAo) * 4u);
                uint4 B = ldsm4(WtB + (unsigned)(rowB * WT_STRIDE + kbase + kk + kBo) * 4u);
                mma_tf32(acc[0], A.x, A.y, A.z, A.w, B.x, B.y);
                mma_tf32(acc[1], A.x, A.y, A.z, A.w, B.z, B.w);
            }
        }

        // epilogue: gates = acc + xg into SMEM
        const int rA = mo + lr;
#pragma unroll
        for (int j = 0; j < 2; j++) {
            const int cl = no + j * 8 + 2 * lc;
            Gs[rA * 33 + cl]           = acc[j][0] + xv[j][0];
            Gs[rA * 33 + cl + 1]       = acc[j][1] + xv[j][1];
            Gs[(rA + 8) * 33 + cl]     = acc[j][2] + xv[j][2];
            Gs[(rA + 8) * 33 + cl + 1] = acc[j][3] + xv[j][3];
        }
        __syncthreads();

        // LSTM cell: 64 batch x 8 units, 2 elems per thread
#pragma unroll
        for (int q = 0; q < 2; q++) {
            int e  = tid + q * 256;
            int m  = e >> 3, du = e & 7;
            float gi = sigmoidf_(Gs[m * 33 + 0 * 8 + du]);
            float gf = sigmoidf_(Gs[m * 33 + 1 * 8 + du]);
            float gg = tanhf    (Gs[m * 33 + 2 * 8 + du]);
            float go = sigmoidf_(Gs[m * 33 + 3 * 8 + du]);
            float cv = gf * Cl[e] + gi * gg;
            Cl[e] = cv;
            hnxt[m * UU + u0 + du] = go * tanhf(cv);
        }

        grid_bar();   // h visible to all CTAs before next step
    }
}

// ============================================================================
extern "C" void kernel_launch(void* const* d_in, const int* in_sizes, int n_in,
                              void* d_out, int out_size)
{
    const float* x  = (const float*)d_in[0];
    const float* h0 = (const float*)d_in[1];
    const float* c0 = (const float*)d_in[2];
    const float* Wx = (const float*)d_in[3];
    const float* Wh = (const float*)d_in[4];
    const float* b  = (const float*)d_in[5];
    float* out = (float*)d_out;

    // init h state (graph replays must reset state)
    cudaMemcpyToSymbolAsync(g_h, h0, (size_t)BB * UU * sizeof(float), 0,
                            cudaMemcpyDeviceToDevice, 0);

    // phase 1: xg = x @ Wx + b  -> g_xg[t][b][n]
    {
        dim3 grid(BB * TT / 64, G4 / 64);
        xg_kernel<<<grid, 256>>>(x, Wx, b);
    }

    // phase 2: persistent recurrence over all 512 steps
    cudaFuncSetAttribute(lstm_persist, cudaFuncAttributeMaxDynamicSharedMemorySize,
                         SMEM_BYTES);
    lstm_persist<<<NCTA, 256, SMEM_BYTES>>>(Wh, c0);

    // final h lives in g_h[0] (t=511 writes parity (511+1)&1 = 0)
    cudaMemcpyFromSymbolAsync(out, g_h, (size_t)BB * UU * sizeof(float), 0,
                              cudaMemcpyDeviceToDevice, 0);
    (void)in_sizes; (void)n_in; (void)out_size;
}

// round 3
// speedup vs baseline: 2.5569x; 1.4912x over previous
#include <cuda_runtime.h>
#include <cuda_fp16.h>
#include <math.h>

// Problem constants (LSTM_Layer_2576980377766)
#define BB   64          // batch
#define TT   512         // timesteps
#define DD   512         // input dim
#define UU   1024        // hidden units
#define G4   4096        // 4*UU
#define NCTA 128         // persistent CTAs (<= 148 SMs, co-resident)

// ---------------- scratch (device globals; no allocation allowed) ----------
__device__ float  g_xg[(size_t)BB * TT * G4];   // 512 MB: x@Wx + b, layout [t][b][4096]
__device__ __half g_xh[(size_t)BB * TT * DD];   // x in fp16
__device__ __half g_hh[2][BB * UU];             // double-buffered hidden state (fp16)
__device__ volatile unsigned g_bar_gen = 0;     // grid barrier generation
__device__ unsigned g_bar_cnt = 0;              // grid barrier arrival count

// ---------------- helpers ---------------------------------------------------
__device__ __forceinline__ void mma16(float c[4], unsigned a0, unsigned a1,
                                      unsigned a2, unsigned a3,
                                      unsigned b0, unsigned b1) {
    asm volatile(
        "mma.sync.aligned.m16n8k16.row.col.f32.f16.f16.f32 "
        "{%0,%1,%2,%3}, {%4,%5,%6,%7}, {%8,%9}, {%0,%1,%2,%3};"
        : "+f"(c[0]), "+f"(c[1]), "+f"(c[2]), "+f"(c[3])
        : "r"(a0), "r"(a1), "r"(a2), "r"(a3), "r"(b0), "r"(b1));
}

__device__ __forceinline__ uint4 ldsm4(unsigned addr) {
    uint4 r;
    asm volatile("ldmatrix.sync.aligned.m8n8.x4.shared.b16 {%0,%1,%2,%3}, [%4];"
                 : "=r"(r.x), "=r"(r.y), "=r"(r.z), "=r"(r.w) : "r"(addr));
    return r;
}

__device__ __forceinline__ float sigmoidf_(float x) { return 1.0f / (1.0f + expf(-x)); }

// k-permutation within a 32-chunk:  logical mma slot (s,p) -> actual k offset.
// Designed so lane lc's A-fragment data = 8 contiguous fp16 at [8*lc .. 8*lc+8).
//   p <  8: actual = 8*(p>>1)     + 4*s +     (p&1)
//   p >= 8: actual = 8*((p-8)>>1) + 4*s + 2 + (p&1)
__device__ __forceinline__ int slot_perm(int slot5) {   // slot5 in [0,32)
    int s = slot5 >> 4, p = slot5 & 15;
    int lcp = (p < 8) ? (p >> 1) : ((p - 8) >> 1);
    int add = (p < 8) ? 0 : 2;
    return 8 * lcp + 4 * s + add + (p & 1);
}

// ============================================================================
// Kernel 0: convert x -> fp16
// ============================================================================
__global__ __launch_bounds__(256) void conv_x(const float* __restrict__ x) {
    const size_t n4 = (size_t)BB * TT * DD / 4;
    for (size_t i = (size_t)blockIdx.x * 256 + threadIdx.x; i < n4;
         i += (size_t)gridDim.x * 256) {
        float4 v = reinterpret_cast<const float4*>(x)[i];
        __half2 h01 = __floats2half2_rn(v.x, v.y);
        __half2 h23 = __floats2half2_rn(v.z, v.w);
        uint2 st;
        st.x = *reinterpret_cast<unsigned*>(&h01);
        st.y = *reinterpret_cast<unsigned*>(&h23);
        reinterpret_cast<uint2*>(g_xh)[i] = st;
    }
}

// ============================================================================
// Kernel 1: xg[t,b,col] = x[b,t,:] @ Wx[:,col] + bias[col]
// 1024 CTAs: (n-slice 0..127) x (m-group 0..7). Wx slice (512x32) fp16 in SMEM
// (k-permuted, n-major). A straight from global (g_xh) into registers.
// Each CTA: 64 M-tiles of 64 rows.
// ============================================================================
#define XG_WT_STRIDE 520   // fp16 per n-row (512 + 8 pad) -> 1040B = 16*65

__global__ __launch_bounds__(256) void xg_kernel(
    const float* __restrict__ Wx, const float* __restrict__ bias)
{
    __shared__ __half Wt[32 * XG_WT_STRIDE];

    const int tid  = threadIdx.x;
    const int warp = tid >> 5, lane = tid & 31;
    const int lr = lane >> 2, lc = lane & 3;
    const int mo = (warp & 3) * 16;
    const int no = (warp >> 2) * 16;
    const int ns = blockIdx.x & 127;       // n-slice
    const int mg = blockIdx.x >> 7;        // m-group
    const int u0 = ns * 8;

    // fill Wt[n][slot] = Wx[32*kc + perm(slot5)][col(n)], fp16 RN
    for (int i = tid; i < 32 * 512; i += 256) {
        int n = i & 31, slotg = i >> 5;
        int k = (slotg & ~31) + slot_perm(slotg & 31);
        int col = (n >> 3) * UU + u0 + (n & 7);
        Wt[n * XG_WT_STRIDE + slotg] = __float2half_rn(Wx[(size_t)k * G4 + col]);
    }
    __syncthreads();

    const unsigned WtB = (unsigned)__cvta_generic_to_shared(Wt);
    const unsigned bAddrBase = WtB
        + (unsigned)(no + ((lane >> 4) << 3) + (lane & 7)) * (XG_WT_STRIDE * 2)
        + ((lane >> 3) & 1) * 16;

    // bias regs (CTA-invariant cols)
    float bv[2][2];
#pragma unroll
    for (int j = 0; j < 2; j++) {
        int cl = no + j * 8 + 2 * lc;
        int colg = (cl >> 3) * UU + u0 + (cl & 7);
        bv[j][0] = bias[colg];
        bv[j][1] = bias[colg + 1];
    }

    for (int mt = 0; mt < 64; mt++) {
        const int r0 = mg * 4096 + mt * 64;
        const __half* pr0 = g_xh + (size_t)(r0 + mo + lr) * DD + 8 * lc;
        const __half* pr1 = pr0 + 8 * DD;

        float acc[2][4];
#pragma unroll
        for (int j = 0; j < 2; j++)
#pragma unroll
            for (int i = 0; i < 4; i++) acc[j][i] = 0.0f;

        uint4 a0c = *reinterpret_cast<const uint4*>(pr0);
        uint4 a1c = *reinterpret_cast<const uint4*>(pr1);
        uint4 a0n = *reinterpret_cast<const uint4*>(pr0 + 32);
        uint4 a1n = *reinterpret_cast<const uint4*>(pr1 + 32);

#pragma unroll
        for (int kc = 0; kc < 16; kc++) {
            uint4 a0f = make_uint4(0, 0, 0, 0), a1f = a0f;
            if (kc < 14) {
                a0f = *reinterpret_cast<const uint4*>(pr0 + (kc + 2) * 32);
                a1f = *reinterpret_cast<const uint4*>(pr1 + (kc + 2) * 32);
            }
            const unsigned ba = bAddrBase + kc * 64;
            uint4 B0 = ldsm4(ba);        // kstep 0: (b0 nt0, b1 nt0, b0 nt1, b1 nt1)
            uint4 B1 = ldsm4(ba + 32);   // kstep 1
            mma16(acc[0], a0c.x, a1c.x, a0c.y, a1c.y, B0.x, B0.y);
            mma16(acc[1], a0c.x, a1c.x, a0c.y, a1c.y, B0.z, B0.w);
            mma16(acc[0], a0c.z, a1c.z, a0c.w, a1c.w, B1.x, B1.y);
            mma16(acc[1], a0c.z, a1c.z, a0c.w, a1c.w, B1.z, B1.w);
            a0c = a0n; a1c = a1n; a0n = a0f; a1n = a1f;
        }

        // epilogue: +bias, scatter to g_xg[t][b][col] (rows r -> b=r>>9, t=r&511)
        const int rA = r0 + mo + lr;
        const int rB = rA + 8;
        const size_t row0 = (size_t)((rA & (TT - 1)) * BB + (rA >> 9)) * G4;
        const size_t row1 = (size_t)((rB & (TT - 1)) * BB + (rB >> 9)) * G4;
#pragma unroll
        for (int j = 0; j < 2; j++) {
            int cl = no + j * 8 + 2 * lc;
            int colg = (cl >> 3) * UU + u0 + (cl & 7);
            *reinterpret_cast<float2*>(&g_xg[row0 + colg]) =
                make_float2(acc[j][0] + bv[j][0], acc[j][1] + bv[j][1]);
            *reinterpret_cast<float2*>(&g_xg[row1 + colg]) =
                make_float2(acc[j][2] + bv[j][0], acc[j][3] + bv[j][1]);
        }
    }
}

// ============================================================================
// Kernel 2: persistent LSTM recurrence. 128 CTAs x 256 threads.
// CTA owns u-slice of 8 hidden units -> 32 gate columns. Wh slice fp16 in SMEM
// (k-permuted). A (h) straight from global fp16 into registers, 2-chunk
// register pipeline, NO syncthreads in the k-loop.
// ============================================================================
#define WT_STRIDE 1032                 // fp16 per n-row (1024 + 8 pad) -> 2064B
#define SMEM_BYTES (32 * WT_STRIDE * 2 + 64 * 33 * 4 + 512 * 4)

__device__ __forceinline__ void grid_bar() {
    __syncthreads();
    if (threadIdx.x == 0) {
        unsigned gen = g_bar_gen;
        __threadfence();                                  // release
        if (atomicAdd(&g_bar_cnt, 1u) == NCTA - 1u) {
            g_bar_cnt = 0;
            __threadfence();
            g_bar_gen = gen + 1;
        } else {
            while (g_bar_gen == gen) { __nanosleep(32); }
        }
        __threadfence();                                  // acquire (CCTL.IVALL)
    }
    __syncthreads();
}

__global__ __launch_bounds__(256) void lstm_persist(
    const float* __restrict__ Wh, const float* __restrict__ h0,
    const float* __restrict__ c0, float* __restrict__ out)
{
    extern __shared__ char smraw[];
    __half* Wt = (__half*)smraw;                         // [32][WT_STRIDE]
    float*  Gs = (float*)(smraw + 32 * WT_STRIDE * 2);   // [64][33]
    float*  Cl = Gs + 64 * 33;                           // [64][8]

    const int tid  = threadIdx.x;
    const int warp = tid >> 5, lane = tid & 31;
    const int lr = lane >> 2, lc = lane & 3;
    const int mo = (warp & 3) * 16;                // 4 warps along M (batch)
    const int no = (warp >> 2) * 16;               // 2 warps along N
    const int u0 = blockIdx.x * 8;

    // ---- one-time: Wh slice -> Wt (fp16, n-major, k-permuted) ----
    for (int i = tid; i < 32 * 1024; i += 256) {
        int n = i & 31, slotg = i >> 5;
        int k = (slotg & ~31) + slot_perm(slotg & 31);
        int col = (n >> 3) * UU + u0 + (n & 7);
        Wt[n * WT_STRIDE + slotg] = __float2half_rn(Wh[(size_t)k * G4 + col]);
    }
    // ---- one-time: cell-state slice ----
    for (int i = tid; i < 512; i += 256)
        Cl[i] = c0[(i >> 3) * UU + u0 + (i & 7)];
    // ---- one-time: h0 -> fp16 (partitioned across CTAs) ----
    for (int i = blockIdx.x * 256 + tid; i < BB * UU; i += NCTA * 256)
        g_hh[0][i] = __float2half_rn(h0[i]);
    __syncthreads();
    grid_bar();

    const unsigned WtB = (unsigned)__cvta_generic_to_shared(Wt);
    const unsigned bAddrBase = WtB
        + (unsigned)(no + ((lane >> 4) << 3) + (lane & 7)) * (WT_STRIDE * 2)
        + ((lane >> 3) & 1) * 16;

    // xv prefetch for t=0
    float xv[2][4];
    {
        const size_t base = 0;
#pragma unroll
        for (int j = 0; j < 2; j++) {
            int cl = no + j * 8 + 2 * lc;
            int colg = (cl >> 3) * UU + u0 + (cl & 7);
            const size_t p0 = base + (size_t)(mo + lr) * G4 + colg;
            const size_t p1 = base + (size_t)(mo + lr + 8) * G4 + colg;
            xv[j][0] = g_xg[p0]; xv[j][1] = g_xg[p0 + 1];
            xv[j][2] = g_xg[p1]; xv[j][3] = g_xg[p1 + 1];
        }
    }

    for (int t = 0; t < TT; t++) {
        const __half* __restrict__ hc = g_hh[t & 1];
        __half*       __restrict__ hn = g_hh[(t + 1) & 1];
        const __half* pr0 = hc + (size_t)(mo + lr) * UU + 8 * lc;
        const __half* pr1 = pr0 + 8 * UU;

        float acc[2][4];
#pragma unroll
        for (int j = 0; j < 2; j++)
#pragma unroll
            for (int i = 0; i < 4; i++) acc[j][i] = 0.0f;

        uint4 a0c = *reinterpret_cast<const uint4*>(pr0);
        uint4 a1c = *reinterpret_cast<const uint4*>(pr1);
        uint4 a0n = *reinterpret_cast<const uint4*>(pr0 + 32);
        uint4 a1n = *reinterpret_cast<const uint4*>(pr1 + 32);

#pragma unroll 8
        for (int kc = 0; kc < 32; kc++) {
            uint4 a0f = make_uint4(0, 0, 0, 0), a1f = a0f;
            if (kc < 30) {
                a0f = *reinterpret_cast<const uint4*>(pr0 + (kc + 2) * 32);
                a1f = *reinterpret_cast<const uint4*>(pr1 + (kc + 2) * 32);
            }
            const unsigned ba = bAddrBase + kc * 64;
            uint4 B0 = ldsm4(ba);
            uint4 B1 = ldsm4(ba + 32);
            mma16(acc[0], a0c.x, a1c.x, a0c.y, a1c.y, B0.x, B0.y);
            mma16(acc[1], a0c.x, a1c.x, a0c.y, a1c.y, B0.z, B0.w);
            mma16(acc[0], a0c.z, a1c.z, a0c.w, a1c.w, B1.x, B1.y);
            mma16(acc[1], a0c.z, a1c.z, a0c.w, a1c.w, B1.z, B1.w);
            a0c = a0n; a1c = a1n; a0n = a0f; a1n = a1f;
        }

        // epilogue: gates = acc + xg into SMEM
        const int rA = mo + lr;
#pragma unroll
        for (int j = 0; j < 2; j++) {
            int cl = no + j * 8 + 2 * lc;
            Gs[rA * 33 + cl]           = acc[j][0] + xv[j][0];
            Gs[rA * 33 + cl + 1]       = acc[j][1] + xv[j][1];
            Gs[(rA + 8) * 33 + cl]     = acc[j][2] + xv[j][2];
            Gs[(rA + 8) * 33 + cl + 1] = acc[j][3] + xv[j][3];
        }
        __syncthreads();

        // LSTM cell: 64 batch x 8 units, 2 elems per thread
#pragma unroll
        for (int q = 0; q < 2; q++) {
            int e  = tid + q * 256;
            int m  = e >> 3, du = e & 7;
            float gi = sigmoidf_(Gs[m * 33 + 0 * 8 + du]);
            float gf = sigmoidf_(Gs[m * 33 + 1 * 8 + du]);
            float gg = tanhf    (Gs[m * 33 + 2 * 8 + du]);
            float go = sigmoidf_(Gs[m * 33 + 3 * 8 + du]);
            float cv = gf * Cl[e] + gi * gg;
            Cl[e] = cv;
            float hv = go * tanhf(cv);
            hn[m * UU + u0 + du] = __float2half_rn(hv);
            if (t == TT - 1) out[m * UU + u0 + du] = hv;
        }

        // prefetch xg for t+1 (hidden behind the barrier)
        if (t + 1 < TT) {
            const size_t base = (size_t)(t + 1) * BB * G4;
#pragma unroll
            for (int j = 0; j < 2; j++) {
                int cl = no + j * 8 + 2 * lc;
                int colg = (cl >> 3) * UU + u0 + (cl & 7);
                const size_t p0 = base + (size_t)(mo + lr) * G4 + colg;
                const size_t p1 = base + (size_t)(mo + lr + 8) * G4 + colg;
                xv[j][0] = g_xg[p0]; xv[j][1] = g_xg[p0 + 1];
                xv[j][2] = g_xg[p1]; xv[j][3] = g_xg[p1 + 1];
            }
        }

        grid_bar();   // h visible to all CTAs before next step
    }
}

// ============================================================================
extern "C" void kernel_launch(void* const* d_in, const int* in_sizes, int n_in,
                              void* d_out, int out_size)
{
    const float* x  = (const float*)d_in[0];
    const float* h0 = (const float*)d_in[1];
    const float* c0 = (const float*)d_in[2];
    const float* Wx = (const float*)d_in[3];
    const float* Wh = (const float*)d_in[4];
    const float* b  = (const float*)d_in[5];
    float* out = (float*)d_out;

    // phase 0: x -> fp16
    conv_x<<<4096, 256>>>(x);

    // phase 1: xg = x @ Wx + b  -> g_xg[t][b][:]
    xg_kernel<<<1024, 256>>>(Wx, b);

    // phase 2: persistent recurrence, writes final h to out
    cudaFuncSetAttribute(lstm_persist, cudaFuncAttributeMaxDynamicSharedMemorySize,
                         SMEM_BYTES);
    lstm_persist<<<NCTA, 256, SMEM_BYTES>>>(Wh, h0, c0, out);

    (void)in_sizes; (void)n_in; (void)out_size;
}

// round 4
// speedup vs baseline: 3.5389x; 1.3841x over previous
#include <cuda_runtime.h>
#include <cuda_fp16.h>
#include <math.h>

// Problem constants (LSTM_Layer_2576980377766)
#define BB   64          // batch
#define TT   512         // timesteps
#define DD   512         // input dim
#define UU   1024        // hidden units
#define G4   4096        // 4*UU
#define NCTA 128         // persistent CTAs (<= 148 SMs, co-resident)

// ---------------- scratch (device globals; no allocation allowed) ----------
__device__ float  g_xg[(size_t)BB * TT * G4];   // 512 MB: x@Wx + b, layout [t][b][4096]
__device__ __align__(16) __half g_xh[(size_t)BB * TT * DD];   // x in fp16
__device__ __align__(16) __half g_hh[2][BB * UU];             // double-buffered h (fp16)
__device__ volatile unsigned g_bar_gen = 0;     // grid barrier generation
__device__ unsigned g_bar_cnt = 0;              // grid barrier arrival count

// ---------------- helpers ---------------------------------------------------
__device__ __forceinline__ void mma16(float c[4], unsigned a0, unsigned a1,
                                      unsigned a2, unsigned a3,
                                      unsigned b0, unsigned b1) {
    asm volatile(
        "mma.sync.aligned.m16n8k16.row.col.f32.f16.f16.f32 "
        "{%0,%1,%2,%3}, {%4,%5,%6,%7}, {%8,%9}, {%0,%1,%2,%3};"
        : "+f"(c[0]), "+f"(c[1]), "+f"(c[2]), "+f"(c[3])
        : "r"(a0), "r"(a1), "r"(a2), "r"(a3), "r"(b0), "r"(b1));
}

__device__ __forceinline__ uint4 ldsm4(unsigned addr) {
    uint4 r;
    asm volatile("ldmatrix.sync.aligned.m8n8.x4.shared.b16 {%0,%1,%2,%3}, [%4];"
                 : "=r"(r.x), "=r"(r.y), "=r"(r.z), "=r"(r.w) : "r"(addr));
    return r;
}

__device__ __forceinline__ void cp16(unsigned dst, const void* src) {
    asm volatile("cp.async.cg.shared.global [%0], [%1], 16;" :: "r"(dst), "l"(src));
}
__device__ __forceinline__ void cp_commit() {
    asm volatile("cp.async.commit_group;");
}

__device__ __forceinline__ float sigmoidf_(float x) { return 1.0f / (1.0f + expf(-x)); }

// k-permutation for xg_kernel's A-from-global scheme (unchanged from R2)
__device__ __forceinline__ int slot_perm(int slot5) {   // slot5 in [0,32)
    int s = slot5 >> 4, p = slot5 & 15;
    int lcp = (p < 8) ? (p >> 1) : ((p - 8) >> 1);
    int add = (p < 8) ? 0 : 2;
    return 8 * lcp + 4 * s + add + (p & 1);
}

// ============================================================================
// Kernel 0: convert x -> fp16
// ============================================================================
__global__ __launch_bounds__(256) void conv_x(const float* __restrict__ x) {
    const size_t n4 = (size_t)BB * TT * DD / 4;
    for (size_t i = (size_t)blockIdx.x * 256 + threadIdx.x; i < n4;
         i += (size_t)gridDim.x * 256) {
        float4 v = reinterpret_cast<const float4*>(x)[i];
        __half2 h01 = __floats2half2_rn(v.x, v.y);
        __half2 h23 = __floats2half2_rn(v.z, v.w);
        uint2 st;
        st.x = *reinterpret_cast<unsigned*>(&h01);
        st.y = *reinterpret_cast<unsigned*>(&h23);
        reinterpret_cast<uint2*>(g_xh)[i] = st;
    }
}

// ============================================================================
// Kernel 1: xg[t,b,col] = x[b,t,:] @ Wx[:,col] + bias[col]   (unchanged R2)
// ============================================================================
#define XG_WT_STRIDE 520   // fp16 per n-row (512 + 8 pad)

__global__ __launch_bounds__(256) void xg_kernel(
    const float* __restrict__ Wx, const float* __restrict__ bias)
{
    __shared__ __half Wt[32 * XG_WT_STRIDE];

    const int tid  = threadIdx.x;
    const int warp = tid >> 5, lane = tid & 31;
    const int lr = lane >> 2, lc = lane & 3;
    const int mo = (warp & 3) * 16;
    const int no = (warp >> 2) * 16;
    const int ns = blockIdx.x & 127;       // n-slice
    const int mg = blockIdx.x >> 7;        // m-group
    const int u0 = ns * 8;

    for (int i = tid; i < 32 * 512; i += 256) {
        int n = i & 31, slotg = i >> 5;
        int k = (slotg & ~31) + slot_perm(slotg & 31);
        int col = (n >> 3) * UU + u0 + (n & 7);
        Wt[n * XG_WT_STRIDE + slotg] = __float2half_rn(Wx[(size_t)k * G4 + col]);
    }
    __syncthreads();

    const unsigned WtB = (unsigned)__cvta_generic_to_shared(Wt);
    const unsigned bAddrBase = WtB
        + (unsigned)(no + ((lane >> 4) << 3) + (lane & 7)) * (XG_WT_STRIDE * 2)
        + ((lane >> 3) & 1) * 16;

    float bv[2][2];
#pragma unroll
    for (int j = 0; j < 2; j++) {
        int cl = no + j * 8 + 2 * lc;
        int colg = (cl >> 3) * UU + u0 + (cl & 7);
        bv[j][0] = bias[colg];
        bv[j][1] = bias[colg + 1];
    }

    for (int mt = 0; mt < 64; mt++) {
        const int r0 = mg * 4096 + mt * 64;
        const __half* pr0 = g_xh + (size_t)(r0 + mo + lr) * DD + 8 * lc;
        const __half* pr1 = pr0 + 8 * DD;

        float acc[2][4];
#pragma unroll
        for (int j = 0; j < 2; j++)
#pragma unroll
            for (int i = 0; i < 4; i++) acc[j][i] = 0.0f;

        uint4 a0c = *reinterpret_cast<const uint4*>(pr0);
        uint4 a1c = *reinterpret_cast<const uint4*>(pr1);
        uint4 a0n = *reinterpret_cast<const uint4*>(pr0 + 32);
        uint4 a1n = *reinterpret_cast<const uint4*>(pr1 + 32);

#pragma unroll
        for (int kc = 0; kc < 16; kc++) {
            uint4 a0f = make_uint4(0, 0, 0, 0), a1f = a0f;
            if (kc < 14) {
                a0f = *reinterpret_cast<const uint4*>(pr0 + (kc + 2) * 32);
                a1f = *reinterpret_cast<const uint4*>(pr1 + (kc + 2) * 32);
            }
            const unsigned ba = bAddrBase + kc * 64;
            uint4 B0 = ldsm4(ba);
            uint4 B1 = ldsm4(ba + 32);
            mma16(acc[0], a0c.x, a1c.x, a0c.y, a1c.y, B0.x, B0.y);
            mma16(acc[1], a0c.x, a1c.x, a0c.y, a1c.y, B0.z, B0.w);
            mma16(acc[0], a0c.z, a1c.z, a0c.w, a1c.w, B1.x, B1.y);
            mma16(acc[1], a0c.z, a1c.z, a0c.w, a1c.w, B1.z, B1.w);
            a0c = a0n; a1c = a1n; a0n = a0f; a1n = a1f;
        }

        const int rA = r0 + mo + lr;
        const int rB = rA + 8;
        const size_t row0 = (size_t)((rA & (TT - 1)) * BB + (rA >> 9)) * G4;
        const size_t row1 = (size_t)((rB & (TT - 1)) * BB + (rB >> 9)) * G4;
#pragma unroll
        for (int j = 0; j < 2; j++) {
            int cl = no + j * 8 + 2 * lc;
            int colg = (cl >> 3) * UU + u0 + (cl & 7);
            *reinterpret_cast<float2*>(&g_xg[row0 + colg]) =
                make_float2(acc[j][0] + bv[j][0], acc[j][1] + bv[j][1]);
            *reinterpret_cast<float2*>(&g_xg[row1 + colg]) =
                make_float2(acc[j][2] + bv[j][0], acc[j][3] + bv[j][1]);
        }
    }
}

// ============================================================================
// Kernel 2: persistent LSTM recurrence. 128 CTAs x 256 threads.
// Per step: h (64x1024 fp16) copied global->SMEM via cp.async.cg (32 groups,
// issued once, waited in 2 halves). All operands via canonical ldmatrix.
// ============================================================================
#define HS_STRIDE 1032                 // fp16 per m-row (1024 + 8 pad)
#define WT_STRIDE 1032                 // fp16 per n-row
#define WT_BYTES  (32 * WT_STRIDE * 2)
#define HS_BYTES  (64 * HS_STRIDE * 2)
#define SMEM_BYTES (WT_BYTES + HS_BYTES + 64 * 33 * 4 + 512 * 4)

__global__ __launch_bounds__(256) void lstm_persist(
    const float* __restrict__ Wh, const float* __restrict__ h0,
    const float* __restrict__ c0, float* __restrict__ out)
{
    extern __shared__ char smraw[];
    __half* Wt = (__half*)smraw;                         // [32][WT_STRIDE]
    __half* Hs = (__half*)(smraw + WT_BYTES);            // [64][HS_STRIDE]
    float*  Gs = (float*)(smraw + WT_BYTES + HS_BYTES);  // [64][33]
    float*  Cl = Gs + 64 * 33;                           // [64][8]

    const int tid  = threadIdx.x;
    const int warp = tid >> 5, lane = tid & 31;
    const int lr = lane >> 2, lc = lane & 3;
    const int mo = (warp & 3) * 16;                // 4 warps along M (batch)
    const int no = (warp >> 2) * 16;               // 2 warps along N
    const int u0 = blockIdx.x * 8;

    // ---- one-time: Wh slice -> Wt (fp16, n-major [n][k], natural k order) ----
    for (int i = tid; i < 32 * 1024; i += 256) {
        int n = i & 31, k = i >> 5;
        int col = (n >> 3) * UU + u0 + (n & 7);
        Wt[n * WT_STRIDE + k] = __float2half_rn(Wh[(size_t)k * G4 + col]);
    }
    // ---- one-time: cell-state slice ----
    for (int i = tid; i < 512; i += 256)
        Cl[i] = c0[(i >> 3) * UU + u0 + (i & 7)];
    // ---- one-time: h0 -> fp16 (partitioned across CTAs) ----
    for (int i = blockIdx.x * 256 + tid; i < BB * UU; i += NCTA * 256)
        g_hh[0][i] = __float2half_rn(h0[i]);
    __syncthreads();

    // initial grid barrier (h0 visible everywhere)
    if (tid == 0) {
        unsigned gen = g_bar_gen;
        __threadfence();
        if (atomicAdd(&g_bar_cnt, 1u) == NCTA - 1u) {
            g_bar_cnt = 0; __threadfence(); g_bar_gen = gen + 1;
        } else {
            while (g_bar_gen == gen) { __nanosleep(32); }
        }
        __threadfence();
    }
    __syncthreads();

    const unsigned HsB = (unsigned)__cvta_generic_to_shared(Hs);
    const unsigned WtB = (unsigned)__cvta_generic_to_shared(Wt);

    // canonical ldmatrix address bases
    const unsigned aBase = HsB
        + (unsigned)((mo + (lane & 15)) * HS_STRIDE + (lane >> 4) * 8) * 2u;
    const unsigned bBase = WtB
        + (unsigned)((no + ((lane >> 4) << 3) + (lane & 7)) * WT_STRIDE
                     + ((lane >> 3) & 1) * 8) * 2u;

    // cp.async roles: thread copies 16B: row = tid>>2, seg = tid&3
    const int cprow = tid >> 2, cpseg = tid & 3;
    const unsigned cpDst = HsB + (unsigned)(cprow * HS_STRIDE + cpseg * 8) * 2u;

    // xv prefetch for t=0
    float xv[2][4];
#pragma unroll
    for (int j = 0; j < 2; j++) {
        int cl = no + j * 8 + 2 * lc;
        int colg = (cl >> 3) * UU + u0 + (cl & 7);
        const size_t p0 = (size_t)(mo + lr) * G4 + colg;
        const size_t p1 = (size_t)(mo + lr + 8) * G4 + colg;
        xv[j][0] = g_xg[p0]; xv[j][1] = g_xg[p0 + 1];
        xv[j][2] = g_xg[p1]; xv[j][3] = g_xg[p1 + 1];
    }

    for (int t = 0; t < TT; t++) {
        const __half* __restrict__ hc = g_hh[t & 1];
        __half*       __restrict__ hn = g_hh[(t + 1) & 1];

        // ---- issue full-h copy: 32 chunks (one 16B cp.async per thread each)
        const __half* cpSrc = hc + (size_t)cprow * UU + cpseg * 8;
#pragma unroll
        for (int kc = 0; kc < 32; kc++) {
            cp16(cpDst + kc * 64, cpSrc + kc * 32);
            cp_commit();
        }

        float acc[2][4];
#pragma unroll
        for (int j = 0; j < 2; j++)
#pragma unroll
            for (int i = 0; i < 4; i++) acc[j][i] = 0.0f;

        // ---- half 1: chunks 0..15
        asm volatile("cp.async.wait_group 16;");
        __syncthreads();
#pragma unroll
        for (int kc = 0; kc < 16; kc++) {
            uint4 A0 = ldsm4(aBase + kc * 64);
            uint4 A1 = ldsm4(aBase + kc * 64 + 32);
            uint4 B0 = ldsm4(bBase + kc * 64);
            uint4 B1 = ldsm4(bBase + kc * 64 + 32);
            mma16(acc[0], A0.x, A0.y, A0.z, A0.w, B0.x, B0.y);
            mma16(acc[1], A0.x, A0.y, A0.z, A0.w, B0.z, B0.w);
            mma16(acc[0], A1.x, A1.y, A1.z, A1.w, B1.x, B1.y);
            mma16(acc[1], A1.x, A1.y, A1.z, A1.w, B1.z, B1.w);
        }
        // ---- half 2: chunks 16..31
        asm volatile("cp.async.wait_group 0;");
        __syncthreads();
#pragma unroll
        for (int kc = 16; kc < 32; kc++) {
            uint4 A0 = ldsm4(aBase + kc * 64);
            uint4 A1 = ldsm4(aBase + kc * 64 + 32);
            uint4 B0 = ldsm4(bBase + kc * 64);
            uint4 B1 = ldsm4(bBase + kc * 64 + 32);
            mma16(acc[0], A0.x, A0.y, A0.z, A0.w, B0.x, B0.y);
            mma16(acc[1], A0.x, A0.y, A0.z, A0.w, B0.z, B0.w);
            mma16(acc[0], A1.x, A1.y, A1.z, A1.w, B1.x, B1.y);
            mma16(acc[1], A1.x, A1.y, A1.z, A1.w, B1.z, B1.w);
        }

        // ---- epilogue: gates = acc + xg into SMEM
        const int rA = mo + lr;
#pragma unroll
        for (int j = 0; j < 2; j++) {
            int cl = no + j * 8 + 2 * lc;
            Gs[rA * 33 + cl]           = acc[j][0] + xv[j][0];
            Gs[rA * 33 + cl + 1]       = acc[j][1] + xv[j][1];
            Gs[(rA + 8) * 33 + cl]     = acc[j][2] + xv[j][2];
            Gs[(rA + 8) * 33 + cl + 1] = acc[j][3] + xv[j][3];
        }
        __syncthreads();

        // ---- LSTM cell: 64 batch x 8 units, 2 elems per thread
#pragma unroll
        for (int q = 0; q < 2; q++) {
            int e  = tid + q * 256;
            int m  = e >> 3, du = e & 7;
            float gi = sigmoidf_(Gs[m * 33 + 0 * 8 + du]);
            float gf = sigmoidf_(Gs[m * 33 + 1 * 8 + du]);
            float gg = tanhf    (Gs[m * 33 + 2 * 8 + du]);
            float go = sigmoidf_(Gs[m * 33 + 3 * 8 + du]);
            float cv = gf * Cl[e] + gi * gg;
            Cl[e] = cv;
            float hv = go * tanhf(cv);
            hn[m * UU + u0 + du] = __float2half_rn(hv);
            if (t == TT - 1) out[m * UU + u0 + du] = hv;
        }
        __syncthreads();   // all hn writes done before arrive

        // ---- split grid barrier: arrive, prefetch xg[t+1], then wait
        unsigned gen;
        if (tid == 0) {
            gen = g_bar_gen;
            __threadfence();                               // release h writes
            if (atomicAdd(&g_bar_cnt, 1u) == NCTA - 1u) {
                g_bar_cnt = 0; __threadfence(); g_bar_gen = gen + 1;
            }
        }
        if (t + 1 < TT) {
            const size_t base = (size_t)(t + 1) * BB * G4;
#pragma unroll
            for (int j = 0; j < 2; j++) {
                int cl = no + j * 8 + 2 * lc;
                int colg = (cl >> 3) * UU + u0 + (cl & 7);
                const size_t p0 = base + (size_t)(mo + lr) * G4 + colg;
                const size_t p1 = base + (size_t)(mo + lr + 8) * G4 + colg;
                xv[j][0] = g_xg[p0]; xv[j][1] = g_xg[p0 + 1];
                xv[j][2] = g_xg[p1]; xv[j][3] = g_xg[p1 + 1];
            }
        }
        if (tid == 0) {
            while (g_bar_gen == gen) { __nanosleep(32); }
            __threadfence();                               // acquire
        }
        __syncthreads();
    }
}

// ============================================================================
extern "C" void kernel_launch(void* const* d_in, const int* in_sizes, int n_in,
                              void* d_out, int out_size)
{
    const float* x  = (const float*)d_in[0];
    const float* h0 = (const float*)d_in[1];
    const float* c0 = (const float*)d_in[2];
    const float* Wx = (const float*)d_in[3];
    const float* Wh = (const float*)d_in[4];
    const float* b  = (const float*)d_in[5];
    float* out = (float*)d_out;

    // phase 0: x -> fp16
    conv_x<<<4096, 256>>>(x);

    // phase 1: xg = x @ Wx + b  -> g_xg[t][b][:]
    xg_kernel<<<1024, 256>>>(Wx, b);

    // phase 2: persistent recurrence, writes final h to out
    cudaFuncSetAttribute(lstm_persist, cudaFuncAttributeMaxDynamicSharedMemorySize,
                         SMEM_BYTES);
    lstm_persist<<<NCTA, 256, SMEM_BYTES>>>(Wh, h0, c0, out);

    (void)in_sizes; (void)n_in; (void)out_size;
}